// round 7
// baseline (speedup 1.0000x reference)
#include <cuda_runtime.h>
#include <math.h>
#include <cstdint>

// Problem dims
#define B_SZ 512
#define T_IN 1125
#define E_SZ 5
#define C_SZ 40
#define L_SZ 216
#define G_SZ 40
#define H_SZ 10
#define KK   125

// ---- persistent scratch ----
__device__ __align__(16) float d_Wcomb[KK*G_SZ];        // [kk][g]
__device__ __align__(16) float d_bg[G_SZ];
__device__ __align__(16) float d_xg[B_SZ*L_SZ*G_SZ];    // [b][t][g]
__device__ int d_flag = 0;

__device__ __forceinline__ float tanh_a(float x) {
    float r; asm("tanh.approx.f32 %0, %1;" : "=f"(r) : "f"(x)); return r;
}
__device__ __forceinline__ uint32_t smem_u32(const void* p) {
    uint32_t a;
    asm("{ .reg .u64 t; cvta.to.shared.u64 t, %1; cvt.u32.u64 %0, t; }" : "=r"(a) : "l"(p));
    return a;
}

// ============================================================
// Kernel 1 (fused): block 0 = weight fold -> d_Wcomb/d_bg + flag.
// blocks 1..1536 = conv tiles (q = id%3, b = id/3), PTILE=72.
// ============================================================
#define CONV_THREADS 192
#define PTILE 72
// smem floats
#define OFF_WS   0                 // 5000
#define OFF_BG   5000              // 40
#define OFF_BSUM 5040              // 1900 used (+4)
#define OFF_BST  6944              // 9000 = 125*72 (x slab 2020 aliased)
#define CONV_SMEM_FLOATS (6944 + 9000)          // 15944
#define CONV_SMEM_BYTES  (CONV_SMEM_FLOATS*4)   // 63776

__global__ void __launch_bounds__(CONV_THREADS) conv_kernel(
        const float* __restrict__ x,
        const float* __restrict__ wt,     // [40][25]
        const float* __restrict__ tb,     // [40]
        const float* __restrict__ ws,     // [40][40][5]
        const float* __restrict__ gamma,
        const float* __restrict__ beta,
        const float* __restrict__ mean,
        const float* __restrict__ var,
        const float* __restrict__ wih,    // [40][40]
        const float* __restrict__ bih,
        const float* __restrict__ bhh)
{
    extern __shared__ float sm[];
    int tid = threadIdx.x;

    if (blockIdx.x == 0) {
        // ---------------- weight fold (one CTA) ----------------
        float* s_ws    = sm + OFF_BST;          // 8000
        float* s_wt    = sm + OFF_BST + 8000;   // 1000 (ends 15944)
        float* s_wih   = sm + OFF_BSUM;         // 1600
        float* s_scale = sm + OFF_BSUM + 1600;  // 40
        float* s_shift = sm + OFF_BSUM + 1640;  // 40
        float* s_tb    = sm + OFF_BSUM + 1680;  // 40
        float* s_cb    = sm + OFF_BSUM + 1720;  // 40 (ends 6800 < 6944)
        float* Tm      = sm;                     // 5000 (Ws region unused here)

        for (int i = tid; i < 2000; i += CONV_THREADS) ((float4*)s_ws)[i]  = ((const float4*)ws)[i];
        for (int i = tid; i < 250;  i += CONV_THREADS) ((float4*)s_wt)[i]  = ((const float4*)wt)[i];
        for (int i = tid; i < 400;  i += CONV_THREADS) ((float4*)s_wih)[i] = ((const float4*)wih)[i];
        if (tid < C_SZ) {
            float sc = gamma[tid] * rsqrtf(var[tid] + 1e-5f);
            s_scale[tid] = sc;
            s_shift[tid] = beta[tid] - mean[tid]*sc;
            s_tb[tid]    = tb[tid];
        }
        __syncthreads();

        // cb[c] = sum_cp tb[cp] * sum_e ws[c,cp,e]
        if (tid < C_SZ) {
            float cbv = 0.f;
            for (int cp = 0; cp < C_SZ; cp++) {
                const float* w5 = &s_ws[tid*200 + cp*E_SZ];
                cbv += s_tb[cp]*(w5[0]+w5[1]+w5[2]+w5[3]+w5[4]);
            }
            s_cb[tid] = cbv;
        }
        __syncthreads();

        // T'[c*125+kk] = scale[c] * sum_cp ws[c,cp,e]*wt[cp,k],  kk = 5k+e
        for (int o = tid; o < 5000; o += CONV_THREADS) {
            int c = o / KK, kkv = o % KK;
            int k = kkv / E_SZ, e = kkv % E_SZ;
            float s = 0.f;
            #pragma unroll 8
            for (int cp = 0; cp < C_SZ; cp++)
                s += s_ws[c*200 + cp*E_SZ + e] * s_wt[cp*25 + k];
            Tm[o] = s * s_scale[c];
        }
        // bg[g] = bih+bhh + sum_c wih[g,c]*(scale[c]*cb[c] + shift[c])
        if (tid < G_SZ) {
            float s = bih[tid] + bhh[tid];
            for (int c = 0; c < C_SZ; c++)
                s += s_wih[tid*C_SZ + c]*(s_scale[c]*s_cb[c] + s_shift[c]);
            d_bg[tid] = s;
        }
        __syncthreads();

        // Wcomb[kk*40+g] = (1/25) sum_c wih[g,c]*T'[c,kk]
        for (int o = tid; o < 5000; o += CONV_THREADS) {
            int kkv = o / G_SZ, g = o % G_SZ;
            float s = 0.f;
            #pragma unroll 8
            for (int c = 0; c < C_SZ; c++)
                s += s_wih[g*C_SZ + c] * Tm[c*KK + kkv];
            d_Wcomb[o] = s * 0.04f;
        }
        __threadfence();
        __syncthreads();
        if (tid == 0)
            asm volatile("st.release.gpu.b32 [%0], %1;" :: "l"(&d_flag), "r"(1) : "memory");
        return;
    }

    // ---------------- conv tile ----------------
    int id = blockIdx.x - 1;
    int q  = id % 3;
    int b  = id / 3;
    float* Ws   = sm + OFF_WS;
    float* bg_s = sm + OFF_BG;
    float* Bsum = sm + OFF_BSUM;
    float* Bst  = sm + OFF_BST;
    float* xs   = Bst;                 // alias: x slab dead before transpose

    const float* xb = x + (size_t)b*(T_IN*E_SZ) + q*(PTILE*5*E_SZ);   // q*1800
    for (int i = tid; i < 2020; i += CONV_THREADS) xs[i] = xb[i];
    __syncthreads();

    // Bsum[t*5+e] = sum_{j<25} xs[(t+j)*5+e], t in [0,380)
    {
        int e = tid % 5, seg = tid / 5;
        int t0 = seg*10;
        if (t0 < 380) {
            int t1 = min(t0+10, 380);
            float s = 0.f;
            #pragma unroll
            for (int j = 0; j < 25; j++) s += xs[(t0+j)*5 + e];
            Bsum[t0*5+e] = s;
            for (int tt = t0+1; tt < t1; tt++) {
                s += xs[(tt+24)*5+e] - xs[(tt-1)*5+e];
                Bsum[tt*5+e] = s;
            }
        }
    }
    __syncthreads();

    // transpose: Bst[kk*72 + pl] = Bsum[(5*pl + k)*5 + e]
    for (int idx = tid; idx < KK*PTILE; idx += CONV_THREADS) {
        int kk = idx / PTILE;
        int pl = idx - kk*PTILE;
        int k  = kk / 5;
        int e  = kk - k*5;
        Bst[idx] = Bsum[(5*pl + k)*5 + e];
    }

    // wait for fold (usually already done), then stage weights
    if (tid == 0) {
        uint32_t f;
        do {
            asm volatile("ld.acquire.gpu.b32 %0, [%1];" : "=r"(f) : "l"(&d_flag) : "memory");
            if (!f) __nanosleep(64);
        } while (!f);
    }
    __syncthreads();
    for (int i = tid; i < KK*G_SZ; i += CONV_THREADS) Ws[i] = d_Wcomb[i];
    if (tid < G_SZ) bg_s[tid] = d_bg[tid];
    __syncthreads();

    if (tid < 180) {
        int gq = tid / 18;            // 0..9  -> gates 4gq..4gq+3
        int pq = tid - gq*18;         // 0..17 -> p 4pq..4pq+3
        const float4* wp = (const float4*)Ws  + gq;    // wp[kk*10]
        const float4* xq = (const float4*)Bst + pq;    // xq[kk*18]

        float4 bg4 = ((const float4*)bg_s)[gq];
        float a00=bg4.x,a01=bg4.x,a02=bg4.x,a03=bg4.x;
        float a10=bg4.y,a11=bg4.y,a12=bg4.y,a13=bg4.y;
        float a20=bg4.z,a21=bg4.z,a22=bg4.z,a23=bg4.z;
        float a30=bg4.w,a31=bg4.w,a32=bg4.w,a33=bg4.w;

        #pragma unroll 5
        for (int kk = 0; kk < KK; kk++) {
            float4 w  = wp[kk*10];
            float4 xv = xq[kk*18];
            a00 = fmaf(w.x, xv.x, a00); a01 = fmaf(w.x, xv.y, a01);
            a02 = fmaf(w.x, xv.z, a02); a03 = fmaf(w.x, xv.w, a03);
            a10 = fmaf(w.y, xv.x, a10); a11 = fmaf(w.y, xv.y, a11);
            a12 = fmaf(w.y, xv.z, a12); a13 = fmaf(w.y, xv.w, a13);
            a20 = fmaf(w.z, xv.x, a20); a21 = fmaf(w.z, xv.y, a21);
            a22 = fmaf(w.z, xv.z, a22); a23 = fmaf(w.z, xv.w, a23);
            a30 = fmaf(w.w, xv.x, a30); a31 = fmaf(w.w, xv.y, a31);
            a32 = fmaf(w.w, xv.z, a32); a33 = fmaf(w.w, xv.w, a33);
        }

        // xg layout [b][t][g]
        int p0 = q*PTILE + 4*pq;
        float* dst = d_xg + (size_t)b*(L_SZ*G_SZ) + p0*G_SZ + 4*gq;
        *(float4*)(dst        ) = make_float4(a00, a10, a20, a30);
        *(float4*)(dst + G_SZ ) = make_float4(a01, a11, a21, a31);
        *(float4*)(dst + 2*G_SZ) = make_float4(a02, a12, a22, a32);
        *(float4*)(dst + 3*G_SZ) = make_float4(a03, a13, a23, a33);
    }
}

// ============================================================
// Kernel 2: LSTM scan + FC. Contiguous warp-private xg slice
// staged via cp.async; resets d_flag for next replay.
// ============================================================
#define LSTM_WARPS 4
#define XSLICE_FLOATS (L_SZ*G_SZ)            // 8640
#define XSLICE_BYTES  (XSLICE_FLOATS*4)      // 34560
#define LSTM_SMEM_BYTES (LSTM_WARPS*XSLICE_BYTES + 256)

__global__ void __launch_bounds__(32*LSTM_WARPS) lstm_kernel(
        const float* __restrict__ whh,  // [40][10]
        const float* __restrict__ fcw,  // [2][10]
        const float* __restrict__ fcb,
        float* __restrict__ out)
{
    extern __shared__ float xsm[];
    int warp = threadIdx.x >> 5;
    int lid  = threadIdx.x & 31;
    int b    = blockIdx.x*LSTM_WARPS + warp;

    if (blockIdx.x == 0 && threadIdx.x == 0) d_flag = 0;   // reset for next replay

    // stage xg[b] (contiguous 34560 B) -> smem slice
    {
        uint32_t dst0 = smem_u32(xsm) + warp*XSLICE_BYTES;
        const char* src0 = (const char*)(d_xg + (size_t)b*XSLICE_FLOATS);
        for (int c = lid; c < 2160; c += 32) {
            uint32_t dst = dst0 + (uint32_t)(c*16);
            const void* src = src0 + (size_t)c*16;
            asm volatile("cp.async.ca.shared.global [%0], [%1], 16;" :: "r"(dst), "l"(src));
        }
        asm volatile("cp.async.commit_group;" ::: "memory");
        asm volatile("cp.async.wait_group 0;" ::: "memory");
        __syncwarp();
    }
    const float* xw = xsm + warp*XSLICE_FLOATS;

    int r = min(lid, 19);
    float wa[H_SZ], wb[H_SZ];
    #pragma unroll
    for (int j = 0; j < H_SZ; j++) {
        wa[j] = whh[r*H_SZ + j];
        wb[j] = whh[(r+20)*H_SZ + j];
    }
    const float sc2 = (lid < 10) ? 1.0f : 0.5f;
    const float k1  = (lid < 10) ? 1.0f : 0.5f;
    const float k0  = (lid < 10) ? 0.0f : 0.5f;

    float h[H_SZ];
    #pragma unroll
    for (int j = 0; j < H_SZ; j++) h[j] = 0.f;
    float c = 0.f;

    float cur1 = xw[r], cur2 = xw[20 + r];
    for (int t = 0; t < L_SZ; t++) {
        float n1 = xw[(t+1)*G_SZ + r];        // overrun at t=215 lands in pad
        float n2 = xw[(t+1)*G_SZ + 20 + r];

        float s1a = cur1, s1b = 0.f, s2a = cur2, s2b = 0.f;
        #pragma unroll
        for (int j = 0; j < 5; j++) {
            s1a = fmaf(wa[j],   h[j],   s1a);
            s1b = fmaf(wa[j+5], h[j+5], s1b);
            s2a = fmaf(wb[j],   h[j],   s2a);
            s2b = fmaf(wb[j+5], h[j+5], s2b);
        }
        float g1 = s1a + s1b;
        float g2 = s2a + s2b;
        float a1 = fmaf(0.5f, tanh_a(0.5f*g1), 0.5f);   // sigmoid: i / f
        float a2 = fmaf(k1,   tanh_a(sc2*g2),  k0);     // tanh g / sigmoid o
        float fv = __shfl_sync(0xffffffffu, a1, lid + 10);
        float ov = __shfl_sync(0xffffffffu, a2, lid + 10);
        c = fmaf(fv, c, a1*a2);
        float hv = ov * tanh_a(c);
        #pragma unroll
        for (int j = 0; j < H_SZ; j++)
            h[j] = __shfl_sync(0xffffffffu, hv, j);
        cur1 = n1; cur2 = n2;
    }

    if (lid < 2) {
        float o = fcb[lid];
        #pragma unroll
        for (int j = 0; j < H_SZ; j++) o = fmaf(fcw[lid*H_SZ + j], h[j], o);
        out[b*2 + lid] = o;
    }
}

// ============================================================
extern "C" void kernel_launch(void* const* d_in, const int* in_sizes, int n_in,
                              void* d_out, int out_size)
{
    const float* x     = (const float*)d_in[0];
    const float* ctw   = (const float*)d_in[1];
    const float* ctb   = (const float*)d_in[2];
    const float* csw   = (const float*)d_in[3];
    const float* gamma = (const float*)d_in[4];
    const float* beta  = (const float*)d_in[5];
    const float* mean  = (const float*)d_in[6];
    const float* var   = (const float*)d_in[7];
    const float* wih   = (const float*)d_in[8];
    const float* whh   = (const float*)d_in[9];
    const float* bih   = (const float*)d_in[10];
    const float* bhh   = (const float*)d_in[11];
    const float* fcw   = (const float*)d_in[12];
    const float* fcb   = (const float*)d_in[13];
    float* out = (float*)d_out;

    cudaFuncSetAttribute(conv_kernel, cudaFuncAttributeMaxDynamicSharedMemorySize, CONV_SMEM_BYTES);
    cudaFuncSetAttribute(lstm_kernel, cudaFuncAttributeMaxDynamicSharedMemorySize, LSTM_SMEM_BYTES);

    conv_kernel<<<1537, CONV_THREADS, CONV_SMEM_BYTES>>>(
        x, ctw, ctb, csw, gamma, beta, mean, var, wih, bih, bhh);
    lstm_kernel<<<B_SZ/LSTM_WARPS, 32*LSTM_WARPS, LSTM_SMEM_BYTES>>>(whh, fcw, fcb, out);
}

// round 8
// speedup vs baseline: 1.1718x; 1.1718x over previous
#include <cuda_runtime.h>
#include <math.h>
#include <cstdint>

// Problem dims
#define B_SZ 512
#define T_IN 1125
#define E_SZ 5
#define C_SZ 40
#define L_SZ 216
#define G_SZ 40
#define H_SZ 10
#define KK   125

// ---- persistent scratch ----
__device__ __align__(16) float d_Wcomb[KK*G_SZ];        // [kk][g]
__device__ __align__(16) float d_bg[G_SZ];
__device__ __align__(16) float d_xg[B_SZ*L_SZ*G_SZ];    // [b][t][g]

__device__ __forceinline__ float tanh_a(float x) {
    float r; asm("tanh.approx.f32 %0, %1;" : "=f"(r) : "f"(x)); return r;
}
__device__ __forceinline__ uint32_t smem_u32(const void* p) {
    uint32_t a;
    asm("{ .reg .u64 t; cvta.to.shared.u64 t, %1; cvt.u32.u64 %0, t; }" : "=r"(a) : "l"(p));
    return a;
}

// ============================================================
// Kernel 0: fold conv_time, conv_spat, BN, avgpool, w_ih, biases
// into Wcomb[125][40] + bg[40]. 40 CTAs, one gate each. (R6-proven)
// ============================================================
__global__ void __launch_bounds__(256) prep_kernel(
        const float* __restrict__ wt,     // [40][25]
        const float* __restrict__ tb,     // [40]
        const float* __restrict__ ws,     // [40][40][5]
        const float* __restrict__ gamma,
        const float* __restrict__ beta,
        const float* __restrict__ mean,
        const float* __restrict__ var,
        const float* __restrict__ wih,    // [40][40]
        const float* __restrict__ bih,
        const float* __restrict__ bhh)
{
    __shared__ __align__(16) float s_ws[C_SZ*C_SZ*E_SZ];   // 8000
    __shared__ __align__(16) float s_wt[C_SZ*25];
    __shared__ float s_wr[C_SZ], s_wsc[C_SZ], s_shift[C_SZ], s_tb[C_SZ];
    __shared__ float A_s[C_SZ*E_SZ];
    __shared__ float red[8];
    int t = threadIdx.x;
    int g = blockIdx.x;

    for (int i = t; i < 2000; i += 256) ((float4*)s_ws)[i] = ((const float4*)ws)[i];
    for (int i = t; i < 250;  i += 256) ((float4*)s_wt)[i] = ((const float4*)wt)[i];
    if (t < C_SZ) {
        float sc = gamma[t] * rsqrtf(var[t] + 1e-5f);
        float wr = wih[g*C_SZ + t];
        s_wr[t]  = wr;
        s_wsc[t] = wr * sc;
        s_shift[t] = beta[t] - mean[t]*sc;
        s_tb[t] = tb[t];
    }
    __syncthreads();

    if (t < C_SZ*E_SZ) {
        int cp = t / E_SZ, e = t % E_SZ;
        float s = 0.f;
        #pragma unroll 8
        for (int c = 0; c < C_SZ; c++) s += s_wsc[c] * s_ws[c*200 + cp*E_SZ + e];
        A_s[t] = s;
    }
    __syncthreads();

    if (t < KK) {
        int k = t / E_SZ, e = t % E_SZ;
        float s = 0.f;
        #pragma unroll 8
        for (int cp = 0; cp < C_SZ; cp++) s += A_s[cp*E_SZ + e] * s_wt[cp*25 + k];
        d_Wcomb[t*G_SZ + g] = s * (1.0f/25.0f);
    }

    float part = 0.f;
    for (int idx = t; idx < 1600; idx += 256) {
        int c = idx / C_SZ, cp = idx % C_SZ;
        const float* w5 = &s_ws[c*200 + cp*E_SZ];
        float s5 = w5[0]+w5[1]+w5[2]+w5[3]+w5[4];
        part += s_wsc[c] * s_tb[cp] * s5;
    }
    if (t < C_SZ) part += s_wr[t] * s_shift[t];
    #pragma unroll
    for (int o = 16; o > 0; o >>= 1) part += __shfl_xor_sync(0xffffffffu, part, o);
    if ((t & 31) == 0) red[t >> 5] = part;
    __syncthreads();
    if (t == 0) {
        float s = red[0]+red[1]+red[2]+red[3]+red[4]+red[5]+red[6]+red[7];
        d_bg[g] = bih[g] + bhh[g] + s;
    }
}

// ============================================================
// Kernel 1: conv/pool/GEMM. Direct-transposed box sums (no Bsum
// buffer, no transpose pass). 56.2 KB smem -> 4 CTAs/SM.
// ============================================================
#define CONV_THREADS 192
#define PTILE 72
// smem floats: xs (2020) aliases Ws (5000); weights loaded after box phase.
#define OFF_WS   0
#define OFF_BG   5000
#define OFF_BST  5040              // 9000 = 125*72
#define CONV_SMEM_FLOATS (5040 + 9000)          // 14040
#define CONV_SMEM_BYTES  (CONV_SMEM_FLOATS*4)   // 56160

__global__ void __launch_bounds__(CONV_THREADS) conv_kernel(const float* __restrict__ x)
{
    extern __shared__ float sm[];
    float* xs   = sm;                  // phase 1-2 only
    float* Ws   = sm + OFF_WS;         // phase 3+ (overwrites xs)
    float* bg_s = sm + OFF_BG;
    float* Bst  = sm + OFF_BST;

    int tid = threadIdx.x;
    int q   = blockIdx.x;              // tile 0..2
    int b   = blockIdx.y;

    const float* xb = x + (size_t)b*(T_IN*E_SZ) + q*(PTILE*5*E_SZ);   // q*1800
    for (int i = tid; i < 2020; i += CONV_THREADS) xs[i] = xb[i];
    __syncthreads();

    // box sums written directly transposed:
    // for t in [0,380): s = sum_{j<25} xs[(t+j)*5+e]
    //   belongs to (pl = t/5 - i, k = t%5 + 5i) for i=0..4 when 0<=pl<72
    //   Bst[(5*(t%5) + 25*i + e)*72 + (t/5 - i)] = s
    {
        int e = tid % 5, seg = tid / 5;      // seg 0..38 (seg 38 inactive)
        int t0 = seg*10;
        if (t0 < 380) {
            float s = 0.f;
            #pragma unroll
            for (int j = 0; j < 25; j++) s += xs[(t0+j)*5 + e];
            #pragma unroll 2
            for (int tt = t0; tt < t0+10; tt++) {
                if (tt > t0) s += xs[(tt+24)*5+e] - xs[(tt-1)*5+e];
                int qd = tt / 5, k0 = tt - 5*qd;
                int base = (5*k0 + e)*PTILE + qd;
                #pragma unroll
                for (int i = 0; i < 5; i++) {
                    int pl = qd - i;
                    if (pl >= 0 && pl < PTILE)
                        Bst[base + i*(25*PTILE) - i] = s;
                }
            }
        }
    }
    __syncthreads();

    // stage weights (xs dead)
    for (int i = tid; i < KK*G_SZ; i += CONV_THREADS) Ws[i] = d_Wcomb[i];
    if (tid < G_SZ) bg_s[tid] = d_bg[tid];
    __syncthreads();

    if (tid < 180) {
        int gq = tid / 18;            // 0..9  -> gates 4gq..4gq+3
        int pq = tid - gq*18;         // 0..17 -> p 4pq..4pq+3
        const float4* wp = (const float4*)Ws  + gq;    // wp[kk*10]
        const float4* xq = (const float4*)Bst + pq;    // xq[kk*18]

        float4 bg4 = ((const float4*)bg_s)[gq];
        float a00=bg4.x,a01=bg4.x,a02=bg4.x,a03=bg4.x;
        float a10=bg4.y,a11=bg4.y,a12=bg4.y,a13=bg4.y;
        float a20=bg4.z,a21=bg4.z,a22=bg4.z,a23=bg4.z;
        float a30=bg4.w,a31=bg4.w,a32=bg4.w,a33=bg4.w;

        #pragma unroll 5
        for (int kk = 0; kk < KK; kk++) {
            float4 w  = wp[kk*10];
            float4 xv = xq[kk*18];
            a00 = fmaf(w.x, xv.x, a00); a01 = fmaf(w.x, xv.y, a01);
            a02 = fmaf(w.x, xv.z, a02); a03 = fmaf(w.x, xv.w, a03);
            a10 = fmaf(w.y, xv.x, a10); a11 = fmaf(w.y, xv.y, a11);
            a12 = fmaf(w.y, xv.z, a12); a13 = fmaf(w.y, xv.w, a13);
            a20 = fmaf(w.z, xv.x, a20); a21 = fmaf(w.z, xv.y, a21);
            a22 = fmaf(w.z, xv.z, a22); a23 = fmaf(w.z, xv.w, a23);
            a30 = fmaf(w.w, xv.x, a30); a31 = fmaf(w.w, xv.y, a31);
            a32 = fmaf(w.w, xv.z, a32); a33 = fmaf(w.w, xv.w, a33);
        }

        // xg layout [b][t][g]
        int p0 = q*PTILE + 4*pq;
        float* dst = d_xg + (size_t)b*(L_SZ*G_SZ) + p0*G_SZ + 4*gq;
        *(float4*)(dst         ) = make_float4(a00, a10, a20, a30);
        *(float4*)(dst +   G_SZ) = make_float4(a01, a11, a21, a31);
        *(float4*)(dst + 2*G_SZ) = make_float4(a02, a12, a22, a32);
        *(float4*)(dst + 3*G_SZ) = make_float4(a03, a13, a23, a33);
    }
}

// ============================================================
// Kernel 2: LSTM scan + FC. 2 batches per warp (ILP across the
// two sequential chains), full xg slices staged via cp.async.
// ============================================================
#define LSTM_WARPS 2
#define BPW 2
#define XSLICE_FLOATS (L_SZ*G_SZ)            // 8640
#define XSLICE_BYTES  (XSLICE_FLOATS*4)      // 34560
#define LSTM_SMEM_BYTES (LSTM_WARPS*BPW*XSLICE_BYTES + 256)

__global__ void __launch_bounds__(32*LSTM_WARPS) lstm_kernel(
        const float* __restrict__ whh,  // [40][10]
        const float* __restrict__ fcw,  // [2][10]
        const float* __restrict__ fcb,
        float* __restrict__ out)
{
    extern __shared__ float xsm[];
    int warp = threadIdx.x >> 5;
    int lid  = threadIdx.x & 31;
    int b0   = blockIdx.x*(LSTM_WARPS*BPW) + warp*BPW;

    // stage xg[b0] and xg[b0+1] (contiguous 34560 B each)
    {
        uint32_t dst0 = smem_u32(xsm) + warp*BPW*XSLICE_BYTES;
        #pragma unroll
        for (int u = 0; u < BPW; u++) {
            const char* src0 = (const char*)(d_xg + (size_t)(b0+u)*XSLICE_FLOATS);
            uint32_t d0 = dst0 + u*XSLICE_BYTES;
            for (int c = lid; c < 2160; c += 32) {
                asm volatile("cp.async.ca.shared.global [%0], [%1], 16;"
                             :: "r"(d0 + (uint32_t)(c*16)), "l"(src0 + (size_t)c*16));
            }
        }
        asm volatile("cp.async.commit_group;" ::: "memory");
        asm volatile("cp.async.wait_group 0;" ::: "memory");
        __syncwarp();
    }
    const float* xw[BPW];
    xw[0] = xsm + warp*BPW*XSLICE_FLOATS;
    xw[1] = xw[0] + XSLICE_FLOATS;

    int r = min(lid, 19);
    float wa[H_SZ], wb[H_SZ];
    #pragma unroll
    for (int j = 0; j < H_SZ; j++) {
        wa[j] = whh[r*H_SZ + j];
        wb[j] = whh[(r+20)*H_SZ + j];
    }
    const float sc2 = (lid < 10) ? 1.0f : 0.5f;
    const float k1  = (lid < 10) ? 1.0f : 0.5f;
    const float k0  = (lid < 10) ? 0.0f : 0.5f;

    float h[BPW][H_SZ], cc[BPW], cur1[BPW], cur2[BPW];
    #pragma unroll
    for (int u = 0; u < BPW; u++) {
        #pragma unroll
        for (int j = 0; j < H_SZ; j++) h[u][j] = 0.f;
        cc[u] = 0.f;
        cur1[u] = xw[u][r];
        cur2[u] = xw[u][20 + r];
    }

    for (int t = 0; t < L_SZ; t++) {
        float n1[BPW], n2[BPW];
        #pragma unroll
        for (int u = 0; u < BPW; u++) {           // overrun at t=215 lands in pad
            n1[u] = xw[u][(t+1)*G_SZ + r];
            n2[u] = xw[u][(t+1)*G_SZ + 20 + r];
        }
        float a1[BPW], a2[BPW];
        #pragma unroll
        for (int u = 0; u < BPW; u++) {
            float s1a = cur1[u], s1b = 0.f, s2a = cur2[u], s2b = 0.f;
            #pragma unroll
            for (int j = 0; j < 5; j++) {
                s1a = fmaf(wa[j],   h[u][j],   s1a);
                s1b = fmaf(wa[j+5], h[u][j+5], s1b);
                s2a = fmaf(wb[j],   h[u][j],   s2a);
                s2b = fmaf(wb[j+5], h[u][j+5], s2b);
            }
            float g1 = s1a + s1b;
            float g2 = s2a + s2b;
            a1[u] = fmaf(0.5f, tanh_a(0.5f*g1), 0.5f);   // sigmoid: i / f
            a2[u] = fmaf(k1,   tanh_a(sc2*g2),  k0);     // tanh g / sigmoid o
        }
        #pragma unroll
        for (int u = 0; u < BPW; u++) {
            float fv = __shfl_sync(0xffffffffu, a1[u], lid + 10);
            float ov = __shfl_sync(0xffffffffu, a2[u], lid + 10);
            cc[u] = fmaf(fv, cc[u], a1[u]*a2[u]);
            float hv = ov * tanh_a(cc[u]);
            #pragma unroll
            for (int j = 0; j < H_SZ; j++)
                h[u][j] = __shfl_sync(0xffffffffu, hv, j);
            cur1[u] = n1[u]; cur2[u] = n2[u];
        }
    }

    if (lid < 2) {
        #pragma unroll
        for (int u = 0; u < BPW; u++) {
            float o = fcb[lid];
            #pragma unroll
            for (int j = 0; j < H_SZ; j++) o = fmaf(fcw[lid*H_SZ + j], h[u][j], o);
            out[(b0+u)*2 + lid] = o;
        }
    }
}

// ============================================================
extern "C" void kernel_launch(void* const* d_in, const int* in_sizes, int n_in,
                              void* d_out, int out_size)
{
    const float* x     = (const float*)d_in[0];
    const float* ctw   = (const float*)d_in[1];
    const float* ctb   = (const float*)d_in[2];
    const float* csw   = (const float*)d_in[3];
    const float* gamma = (const float*)d_in[4];
    const float* beta  = (const float*)d_in[5];
    const float* mean  = (const float*)d_in[6];
    const float* var   = (const float*)d_in[7];
    const float* wih   = (const float*)d_in[8];
    const float* whh   = (const float*)d_in[9];
    const float* bih   = (const float*)d_in[10];
    const float* bhh   = (const float*)d_in[11];
    const float* fcw   = (const float*)d_in[12];
    const float* fcb   = (const float*)d_in[13];
    float* out = (float*)d_out;

    cudaFuncSetAttribute(conv_kernel, cudaFuncAttributeMaxDynamicSharedMemorySize, CONV_SMEM_BYTES);
    cudaFuncSetAttribute(lstm_kernel, cudaFuncAttributeMaxDynamicSharedMemorySize, LSTM_SMEM_BYTES);

    prep_kernel<<<G_SZ, 256>>>(ctw, ctb, csw, gamma, beta, mean, var, wih, bih, bhh);
    conv_kernel<<<dim3(3, B_SZ), CONV_THREADS, CONV_SMEM_BYTES>>>(x);
    lstm_kernel<<<B_SZ/(LSTM_WARPS*BPW), 32*LSTM_WARPS, LSTM_SMEM_BYTES>>>(whh, fcw, fcb, out);
}